// round 3
// baseline (speedup 1.0000x reference)
#include <cuda_runtime.h>
#include <cuda_pipeline_primitives.h>

#define NV 8192
#define DIN 256
#define FD 128
#define MAXE 640
#define NF (NV*FD)
#define CCH 64
#define FULLMASK 0xFFFFFFFFu

// ---------------- device scratch (no runtime allocation allowed) ----------------
__device__ float g_proj[2 * NF];               // [h][n][f]
__device__ float g_res[NF];                    // x @ W_res^T
__device__ float g_vals[NF];                   // head-mean attention output
__device__ unsigned short g_cols[NV * MAXE];   // CSR col indices (bits 14/13: head sign flags after k4)
__device__ int   g_rowcnt[NV];
__device__ float g_ssrc[2 * NV], g_ea[2 * NV], g_ea2[2 * NV];
__device__ float g_stgt[2 * NV], g_eb[2 * NV], g_eb2[2 * NV];
__device__ float g_PQ[4 * NV];                 // [h0P, h0Q, h1P, h1Q]
__device__ float4 g_coefpk[NV];                // {czp0, czn0, czp1, czn1}
__device__ float4 g_rowea[NV];                 // {ea0, ea20, ea1, ea21}
__device__ double g_sum[2];                    // sum, sumsq

// ---------------- K0: zero accumulators (every graph replay) ----------------
__global__ void k0_zero() {
    int i = blockIdx.x * 256 + threadIdx.x;
    if (i < 4 * NV) g_PQ[i] = 0.0f;
    if (i < 2) g_sum[i] = 0.0;
}

// ---------------- K1: fused SGEMM  C = x @ [W0 | W1 | Wres^T] ----------------
__global__ __launch_bounds__(256) void k1_gemm(const float* __restrict__ x,
                                               const float* __restrict__ W,
                                               const float* __restrict__ Wres) {
    __shared__ float As[16][132];
    __shared__ float Bs[16][128];
    const int m0 = blockIdx.x * 128;
    const int which = blockIdx.y;
    const int tid = threadIdx.x;
    const int tx = tid & 15, ty = tid >> 4;

    float acc[8][8];
#pragma unroll
    for (int i = 0; i < 8; i++)
#pragma unroll
        for (int j = 0; j < 8; j++) acc[i][j] = 0.0f;

    const int mA = tid >> 1;
    const int kA = (tid & 1) * 8;

    for (int k0 = 0; k0 < DIN; k0 += 16) {
        {
            const float* src = x + (size_t)(m0 + mA) * DIN + k0 + kA;
            float4 v0 = *(const float4*)(src);
            float4 v1 = *(const float4*)(src + 4);
            As[kA + 0][mA] = v0.x; As[kA + 1][mA] = v0.y;
            As[kA + 2][mA] = v0.z; As[kA + 3][mA] = v0.w;
            As[kA + 4][mA] = v1.x; As[kA + 5][mA] = v1.y;
            As[kA + 6][mA] = v1.z; As[kA + 7][mA] = v1.w;
        }
        if (which < 2) {
            int k = tid >> 4, f = (tid & 15) * 8;
            const float* src = W + ((size_t)which * DIN + (k0 + k)) * FD + f;
            float4 v0 = *(const float4*)(src);
            float4 v1 = *(const float4*)(src + 4);
            *(float4*)&Bs[k][f] = v0;
            *(float4*)&Bs[k][f + 4] = v1;
        } else {
            int f = tid >> 1;
            const float* src = Wres + (size_t)f * DIN + k0 + kA;
            float4 v0 = *(const float4*)(src);
            float4 v1 = *(const float4*)(src + 4);
            Bs[kA + 0][f] = v0.x; Bs[kA + 1][f] = v0.y;
            Bs[kA + 2][f] = v0.z; Bs[kA + 3][f] = v0.w;
            Bs[kA + 4][f] = v1.x; Bs[kA + 5][f] = v1.y;
            Bs[kA + 6][f] = v1.z; Bs[kA + 7][f] = v1.w;
        }
        __syncthreads();

#pragma unroll
        for (int kk = 0; kk < 16; kk++) {
            float4 ra0 = *(const float4*)&As[kk][ty * 8];
            float4 ra1 = *(const float4*)&As[kk][ty * 8 + 4];
            float4 rb0 = *(const float4*)&Bs[kk][tx * 8];
            float4 rb1 = *(const float4*)&Bs[kk][tx * 8 + 4];
            float ra[8] = {ra0.x, ra0.y, ra0.z, ra0.w, ra1.x, ra1.y, ra1.z, ra1.w};
            float rb[8] = {rb0.x, rb0.y, rb0.z, rb0.w, rb1.x, rb1.y, rb1.z, rb1.w};
#pragma unroll
            for (int i = 0; i < 8; i++)
#pragma unroll
                for (int j = 0; j < 8; j++) acc[i][j] += ra[i] * rb[j];
        }
        __syncthreads();
    }

    float* dst = (which < 2) ? &g_proj[(size_t)which * NF] : g_res;
#pragma unroll
    for (int i = 0; i < 8; i++) {
        int row = m0 + ty * 8 + i;
        float4 w0 = make_float4(acc[i][0], acc[i][1], acc[i][2], acc[i][3]);
        float4 w1 = make_float4(acc[i][4], acc[i][5], acc[i][6], acc[i][7]);
        *(float4*)&dst[(size_t)row * FD + tx * 8]     = w0;
        *(float4*)&dst[(size_t)row * FD + tx * 8 + 4] = w1;
    }
}

// ---------------- K2: per-node dots + 8 exps (+ packed rowea) ----------------
__global__ __launch_bounds__(256) void k2_scal(const float* __restrict__ asrc,
                                               const float* __restrict__ atgt) {
    int w = blockIdx.x * 8 + (threadIdx.x >> 5);
    int lane = threadIdx.x & 31;
    if (w >= 2 * NV) return;
    int h = w >> 13;
    const float* pr = &g_proj[(size_t)w * FD];
    const float* as = asrc + h * FD;
    const float* at = atgt + h * FD;
    float s1 = 0.0f, s2 = 0.0f;
#pragma unroll
    for (int j = 0; j < 4; j++) {
        float p = pr[lane + 32 * j];
        s1 += p * as[lane + 32 * j];
        s2 += p * at[lane + 32 * j];
    }
#pragma unroll
    for (int o = 16; o; o >>= 1) {
        s1 += __shfl_xor_sync(FULLMASK, s1, o);
        s2 += __shfl_xor_sync(FULLMASK, s2, o);
    }
    if (lane == 0) {
        float ea = expf(s1), ea2 = expf(0.2f * s1);
        g_ssrc[w] = s1; g_ea[w] = ea; g_ea2[w] = ea2;
        g_stgt[w] = s2; g_eb[w] = expf(s2); g_eb2[w] = expf(0.2f * s2);
        ((float2*)&g_rowea[w & (NV - 1)])[h] = make_float2(ea, ea2);
    }
}

// ---------------- K3: single mask pass: copy-out + CSR build (MLP=4) ----------------
__global__ __launch_bounds__(256) void k3_mask(const float4* __restrict__ conn,
                                               float4* __restrict__ outmask) {
    int m = blockIdx.x * 8 + (threadIdx.x >> 5);
    int lane = threadIdx.x & 31;
    const float4* src = conn + (size_t)m * (NV / 4);
    float4* dst = outmask + (size_t)m * (NV / 4);
    unsigned short* cols = &g_cols[(size_t)m * MAXE];
    int cnt = 0;
    for (int it = 0; it < NV / 512; it++) {   // 16 iterations, 4 front-batched LDG.128
        float4 v[4];
#pragma unroll
        for (int j = 0; j < 4; j++) v[j] = src[it * 128 + j * 32 + lane];
#pragma unroll
        for (int j = 0; j < 4; j++) dst[it * 128 + j * 32 + lane] = v[j];
#pragma unroll
        for (int j = 0; j < 4; j++) {
            unsigned b0 = __ballot_sync(FULLMASK, v[j].x == 0.0f);
            unsigned b1 = __ballot_sync(FULLMASK, v[j].y == 0.0f);
            unsigned b2 = __ballot_sync(FULLMASK, v[j].z == 0.0f);
            unsigned b3 = __ballot_sync(FULLMASK, v[j].w == 0.0f);
            unsigned lt = (1u << lane) - 1u;
            int o = cnt + __popc(b0 & lt) + __popc(b1 & lt) + __popc(b2 & lt) + __popc(b3 & lt);
            int col0 = it * 512 + j * 128 + lane * 4;
            if (v[j].x == 0.0f) { if (o < MAXE) cols[o] = (unsigned short)(col0);     o++; }
            if (v[j].y == 0.0f) { if (o < MAXE) cols[o] = (unsigned short)(col0 + 1); o++; }
            if (v[j].z == 0.0f) { if (o < MAXE) cols[o] = (unsigned short)(col0 + 2); o++; }
            if (v[j].w == 0.0f) { if (o < MAXE) cols[o] = (unsigned short)(col0 + 3); o++; }
            cnt += __popc(b0) + __popc(b1) + __popc(b2) + __popc(b3);
        }
    }
    if (lane == 0) g_rowcnt[m] = min(cnt, MAXE);
}

// ---------------- K4: sign-split column sums P/Q + pack sign bits into CSR ----------------
__global__ __launch_bounds__(256) void k4_z() {
    int m = blockIdx.x * 8 + (threadIdx.x >> 5);
    int lane = threadIdx.x & 31;
    int cnt = g_rowcnt[m];
    float ss0 = g_ssrc[m],      ea0 = g_ea[m],      ea20 = g_ea2[m];
    float ss1 = g_ssrc[NV + m], ea1 = g_ea[NV + m], ea21 = g_ea2[NV + m];
    unsigned short* cols = &g_cols[(size_t)m * MAXE];
    for (int e = lane; e < cnt; e += 32) {
        unsigned c = cols[e];
        int n = (int)c;
        float st0 = g_stgt[n], st1 = g_stgt[NV + n];
        if (ss0 + st0 > 0.0f) { atomicAdd(&g_PQ[n], ea0);          c |= 0x4000u; }
        else                  { atomicAdd(&g_PQ[NV + n], ea20); }
        if (ss1 + st1 > 0.0f) { atomicAdd(&g_PQ[2 * NV + n], ea1); c |= 0x2000u; }
        else                  { atomicAdd(&g_PQ[3 * NV + n], ea21); }
        cols[e] = (unsigned short)c;
    }
}

// ---------------- K5: fold Z into packed per-column coefficients ----------------
__global__ void k5_cz() {
    int n = blockIdx.x * 256 + threadIdx.x;
    if (n >= NV) return;
    float Z0 = g_eb[n] * g_PQ[n] + g_eb2[n] * g_PQ[NV + n];
    float Z1 = g_eb[NV + n] * g_PQ[2 * NV + n] + g_eb2[NV + n] * g_PQ[3 * NV + n];
    g_coefpk[n] = make_float4(0.5f * g_eb[n] / Z0,       0.5f * g_eb2[n] / Z0,
                              0.5f * g_eb[NV + n] / Z1,  0.5f * g_eb2[NV + n] / Z1);
}

// ---------------- K6: smem-staged double-buffered SpMM ----------------
__device__ __forceinline__ void fillchunk(float* smem, float4* sC, int buf, int ch, int tid) {
    const int c0 = ch * CCH;
    float* d0 = smem + buf * (2 * CCH * FD);
    const float* s0 = g_proj + (size_t)c0 * FD;
    const float* s1 = g_proj + NF + (size_t)c0 * FD;
#pragma unroll
    for (int i = tid; i < CCH * FD / 4; i += 256) {
        __pipeline_memcpy_async(d0 + i * 4,            s0 + i * 4, 16);
        __pipeline_memcpy_async(d0 + CCH * FD + i * 4, s1 + i * 4, 16);
    }
    if (tid < CCH)
        __pipeline_memcpy_async(&sC[buf * CCH + tid], &g_coefpk[c0 + tid], 16);
}

__global__ __launch_bounds__(256) void k6_spmm() {
    extern __shared__ float smem[];                      // [2][2][CCH][FD] feats
    float4* sC = (float4*)(smem + 2 * 2 * CCH * FD);     // [2][CCH] coefs
    const int tid = threadIdx.x, wid = tid >> 5, lane = tid & 31;
    const int row0 = blockIdx.x * 64 + wid * 8;

    int cur[8], rcnt[8];
    float4 acc[8];
#pragma unroll
    for (int r = 0; r < 8; r++) {
        cur[r] = 0;
        rcnt[r] = g_rowcnt[row0 + r];
        acc[r] = make_float4(0.0f, 0.0f, 0.0f, 0.0f);
    }

    fillchunk(smem, sC, 0, 0, tid);
    __pipeline_commit();

    for (int ch = 0; ch < NV / CCH; ch++) {
        if (ch + 1 < NV / CCH) {
            fillchunk(smem, sC, (ch + 1) & 1, ch + 1, tid);
            __pipeline_commit();
            __pipeline_wait_prior(1);
        } else {
            __pipeline_wait_prior(0);
        }
        __syncthreads();
        const int buf = ch & 1;
        const int c0 = ch * CCH, c1 = c0 + CCH;
        const float* sf0 = smem + buf * (2 * CCH * FD);
        const float* sf1 = sf0 + CCH * FD;
        const float4* sc = sC + buf * CCH;
#pragma unroll
        for (int r = 0; r < 8; r++) {
            const int row = row0 + r;
            const unsigned short* cp = &g_cols[(size_t)row * MAXE];
            const float4 re = __ldg(&g_rowea[row]);
            int e = cur[r];
            const int cnt = rcnt[r];
            while (e < cnt) {
                const unsigned c = cp[e];
                const int n = (int)(c & 0x1FFFu);
                if (n >= c1) break;
                const float4 q = sc[n - c0];
                const float cf0 = (c & 0x4000u) ? re.x * q.x : re.y * q.y;
                const float cf1 = (c & 0x2000u) ? re.z * q.z : re.w * q.w;
                const float4 a = *(const float4*)(sf0 + (n - c0) * FD + lane * 4);
                const float4 b = *(const float4*)(sf1 + (n - c0) * FD + lane * 4);
                acc[r].x += cf0 * a.x + cf1 * b.x;
                acc[r].y += cf0 * a.y + cf1 * b.y;
                acc[r].z += cf0 * a.z + cf1 * b.z;
                acc[r].w += cf0 * a.w + cf1 * b.w;
                e++;
            }
            cur[r] = e;
        }
        __syncthreads();
    }
#pragma unroll
    for (int r = 0; r < 8; r++)
        *(float4*)&g_vals[(size_t)(row0 + r) * FD + lane * 4] = acc[r];
}

// ---------------- K7: instance-norm stats (double accumulation) ----------------
__global__ __launch_bounds__(256) void k7_stats() {
    __shared__ double sdat[2][8];
    double s = 0.0, s2 = 0.0;
    for (int i = blockIdx.x * 256 + threadIdx.x; i < NF; i += gridDim.x * 256) {
        double v = (double)g_vals[i];
        s += v; s2 += v * v;
    }
#pragma unroll
    for (int o = 16; o; o >>= 1) {
        s  += __shfl_xor_sync(FULLMASK, s, o);
        s2 += __shfl_xor_sync(FULLMASK, s2, o);
    }
    int wid = threadIdx.x >> 5, lane = threadIdx.x & 31;
    if (lane == 0) { sdat[0][wid] = s; sdat[1][wid] = s2; }
    __syncthreads();
    if (threadIdx.x == 0) {
        double t = 0.0, t2 = 0.0;
        for (int i = 0; i < 8; i++) { t += sdat[0][i]; t2 += sdat[1][i]; }
        atomicAdd(&g_sum[0], t);
        atomicAdd(&g_sum[1], t2);
    }
}

// ---------------- K8: normalize + residual + ELU ----------------
__global__ void k8_final(float* __restrict__ out) {
    int i = blockIdx.x * 256 + threadIdx.x;
    if (i >= NF) return;
    double mu_d = g_sum[0] / (double)NF;
    double var_d = g_sum[1] / (double)NF - mu_d * mu_d;
    float mu = (float)mu_d;
    float inv = rsqrtf((float)var_d + 1e-5f);
    float v = (g_vals[i] - mu) * inv + g_res[i];
    out[i] = v > 0.0f ? v : expm1f(v);
}

// ---------------- launch ----------------
extern "C" void kernel_launch(void* const* d_in, const int* in_sizes, int n_in,
                              void* d_out, int out_size) {
    const float* x    = (const float*)d_in[0];
    const float* conn = (const float*)d_in[1];
    const float* W    = (const float*)d_in[2];
    const float* asrc = (const float*)d_in[3];
    const float* atgt = (const float*)d_in[4];
    const float* wres = (const float*)d_in[5];
    float* out = (float*)d_out;
    float* outmask = out + NF;

    const int k6_smem = (2 * 2 * CCH * FD) * 4 + 2 * CCH * 16;   // 131072 + 2048
    static int smem_set = 0;
    if (!smem_set) {
        cudaFuncSetAttribute(k6_spmm, cudaFuncAttributeMaxDynamicSharedMemorySize, k6_smem);
        smem_set = 1;
    }

    k0_zero<<<128, 256>>>();
    k1_gemm<<<dim3(64, 3), 256>>>(x, W, wres);
    k2_scal<<<2048, 256>>>(asrc, atgt);
    k3_mask<<<1024, 256>>>((const float4*)conn, (float4*)outmask);
    k4_z<<<1024, 256>>>();
    k5_cz<<<32, 256>>>();
    k6_spmm<<<128, 256, k6_smem>>>();
    k7_stats<<<512, 256>>>();
    k8_final<<<NF / 256, 256>>>(out);
}

// round 4
// speedup vs baseline: 1.5174x; 1.5174x over previous
#include <cuda_runtime.h>
#include <cuda_fp16.h>

#define NV 8192
#define DIN 256
#define FD 128
#define MAXE 640
#define NF (NV*FD)
#define FULLMASK 0xFFFFFFFFu

// ---------------- device scratch (no runtime allocation allowed) ----------------
__device__ float g_proj[2 * NF];               // [h][n][f] fp32
__device__ __half g_projh[2 * NF];             // [n][h][f] fp16 interleaved (512B per node)
__device__ float g_res[NF];                    // x @ W_res^T
__device__ float g_vals[NF];                   // head-mean attention output
__device__ unsigned short g_cols[NV * MAXE];   // CSR cols (bits 14/13 = head sign flags after k4)
__device__ int   g_rowcnt[NV];
__device__ float g_ssrc[2 * NV], g_ea[2 * NV], g_ea2[2 * NV];
__device__ float g_stgt[2 * NV], g_eb[2 * NV], g_eb2[2 * NV];
__device__ float g_PQ[4 * NV];                 // [h0P, h0Q, h1P, h1Q]
__device__ float4 g_coefpk[NV];                // {czp0, czn0, czp1, czn1}
__device__ float4 g_rowea[NV];                 // {ea0, ea20, ea1, ea21}
__device__ double g_sum[2];                    // sum, sumsq

// ---------------- K0: zero accumulators (every graph replay) ----------------
__global__ void k0_zero() {
    int i = blockIdx.x * 256 + threadIdx.x;
    if (i < 4 * NV) g_PQ[i] = 0.0f;
    if (i < 2) g_sum[i] = 0.0;
}

// ---------------- K1: fused SGEMM  C = x @ [W0 | W1 | Wres^T] ----------------
__global__ __launch_bounds__(256) void k1_gemm(const float* __restrict__ x,
                                               const float* __restrict__ W,
                                               const float* __restrict__ Wres) {
    __shared__ float As[16][132];
    __shared__ float Bs[16][128];
    const int m0 = blockIdx.x * 128;
    const int which = blockIdx.y;
    const int tid = threadIdx.x;
    const int tx = tid & 15, ty = tid >> 4;

    float acc[8][8];
#pragma unroll
    for (int i = 0; i < 8; i++)
#pragma unroll
        for (int j = 0; j < 8; j++) acc[i][j] = 0.0f;

    const int mA = tid >> 1;
    const int kA = (tid & 1) * 8;

    for (int k0 = 0; k0 < DIN; k0 += 16) {
        {
            const float* src = x + (size_t)(m0 + mA) * DIN + k0 + kA;
            float4 v0 = *(const float4*)(src);
            float4 v1 = *(const float4*)(src + 4);
            As[kA + 0][mA] = v0.x; As[kA + 1][mA] = v0.y;
            As[kA + 2][mA] = v0.z; As[kA + 3][mA] = v0.w;
            As[kA + 4][mA] = v1.x; As[kA + 5][mA] = v1.y;
            As[kA + 6][mA] = v1.z; As[kA + 7][mA] = v1.w;
        }
        if (which < 2) {
            int k = tid >> 4, f = (tid & 15) * 8;
            const float* src = W + ((size_t)which * DIN + (k0 + k)) * FD + f;
            float4 v0 = *(const float4*)(src);
            float4 v1 = *(const float4*)(src + 4);
            *(float4*)&Bs[k][f] = v0;
            *(float4*)&Bs[k][f + 4] = v1;
        } else {
            int f = tid >> 1;
            const float* src = Wres + (size_t)f * DIN + k0 + kA;
            float4 v0 = *(const float4*)(src);
            float4 v1 = *(const float4*)(src + 4);
            Bs[kA + 0][f] = v0.x; Bs[kA + 1][f] = v0.y;
            Bs[kA + 2][f] = v0.z; Bs[kA + 3][f] = v0.w;
            Bs[kA + 4][f] = v1.x; Bs[kA + 5][f] = v1.y;
            Bs[kA + 6][f] = v1.z; Bs[kA + 7][f] = v1.w;
        }
        __syncthreads();

#pragma unroll
        for (int kk = 0; kk < 16; kk++) {
            float4 ra0 = *(const float4*)&As[kk][ty * 8];
            float4 ra1 = *(const float4*)&As[kk][ty * 8 + 4];
            float4 rb0 = *(const float4*)&Bs[kk][tx * 8];
            float4 rb1 = *(const float4*)&Bs[kk][tx * 8 + 4];
            float ra[8] = {ra0.x, ra0.y, ra0.z, ra0.w, ra1.x, ra1.y, ra1.z, ra1.w};
            float rb[8] = {rb0.x, rb0.y, rb0.z, rb0.w, rb1.x, rb1.y, rb1.z, rb1.w};
#pragma unroll
            for (int i = 0; i < 8; i++)
#pragma unroll
                for (int j = 0; j < 8; j++) acc[i][j] += ra[i] * rb[j];
        }
        __syncthreads();
    }

    float* dst = (which < 2) ? &g_proj[(size_t)which * NF] : g_res;
#pragma unroll
    for (int i = 0; i < 8; i++) {
        int row = m0 + ty * 8 + i;
        float4 w0 = make_float4(acc[i][0], acc[i][1], acc[i][2], acc[i][3]);
        float4 w1 = make_float4(acc[i][4], acc[i][5], acc[i][6], acc[i][7]);
        *(float4*)&dst[(size_t)row * FD + tx * 8]     = w0;
        *(float4*)&dst[(size_t)row * FD + tx * 8 + 4] = w1;
    }
}

// ---------------- K1c: fp32 proj -> fp16 interleaved [n][h][f] ----------------
__global__ void k1c_half() {
    int i = blockIdx.x * 256 + threadIdx.x;       // over NF/2 half2 slots
    int n = i >> 6, f2 = i & 63;
    float2 a = *(const float2*)&g_proj[(size_t)n * FD + f2 * 2];
    float2 b = *(const float2*)&g_proj[NF + (size_t)n * FD + f2 * 2];
    ((half2*)g_projh)[(size_t)n * 128 + f2]      = __floats2half2_rn(a.x, a.y);
    ((half2*)g_projh)[(size_t)n * 128 + 64 + f2] = __floats2half2_rn(b.x, b.y);
}

// ---------------- K2: per-node dots + 8 exps (+ packed rowea) ----------------
__global__ __launch_bounds__(256) void k2_scal(const float* __restrict__ asrc,
                                               const float* __restrict__ atgt) {
    int w = blockIdx.x * 8 + (threadIdx.x >> 5);
    int lane = threadIdx.x & 31;
    if (w >= 2 * NV) return;
    int h = w >> 13;
    const float* pr = &g_proj[(size_t)w * FD];
    const float* as = asrc + h * FD;
    const float* at = atgt + h * FD;
    float s1 = 0.0f, s2 = 0.0f;
#pragma unroll
    for (int j = 0; j < 4; j++) {
        float p = pr[lane + 32 * j];
        s1 += p * as[lane + 32 * j];
        s2 += p * at[lane + 32 * j];
    }
#pragma unroll
    for (int o = 16; o; o >>= 1) {
        s1 += __shfl_xor_sync(FULLMASK, s1, o);
        s2 += __shfl_xor_sync(FULLMASK, s2, o);
    }
    if (lane == 0) {
        float ea = expf(s1), ea2 = expf(0.2f * s1);
        g_ssrc[w] = s1; g_ea[w] = ea; g_ea2[w] = ea2;
        g_stgt[w] = s2; g_eb[w] = expf(s2); g_eb2[w] = expf(0.2f * s2);
        ((float2*)&g_rowea[w & (NV - 1)])[h] = make_float2(ea, ea2);
    }
}

// ---------------- K3: single mask pass: copy-out + CSR build (MLP=4, streaming) ----------------
__global__ __launch_bounds__(256) void k3_mask(const float4* __restrict__ conn,
                                               float4* __restrict__ outmask) {
    int m = blockIdx.x * 8 + (threadIdx.x >> 5);
    int lane = threadIdx.x & 31;
    const float4* src = conn + (size_t)m * (NV / 4);
    float4* dst = outmask + (size_t)m * (NV / 4);
    unsigned short* cols = &g_cols[(size_t)m * MAXE];
    int cnt = 0;
    for (int it = 0; it < NV / 512; it++) {
        float4 v[4];
#pragma unroll
        for (int j = 0; j < 4; j++) v[j] = __ldcs(&src[it * 128 + j * 32 + lane]);
#pragma unroll
        for (int j = 0; j < 4; j++) __stcs(&dst[it * 128 + j * 32 + lane], v[j]);
#pragma unroll
        for (int j = 0; j < 4; j++) {
            unsigned b0 = __ballot_sync(FULLMASK, v[j].x == 0.0f);
            unsigned b1 = __ballot_sync(FULLMASK, v[j].y == 0.0f);
            unsigned b2 = __ballot_sync(FULLMASK, v[j].z == 0.0f);
            unsigned b3 = __ballot_sync(FULLMASK, v[j].w == 0.0f);
            unsigned lt = (1u << lane) - 1u;
            int o = cnt + __popc(b0 & lt) + __popc(b1 & lt) + __popc(b2 & lt) + __popc(b3 & lt);
            int col0 = it * 512 + j * 128 + lane * 4;
            if (v[j].x == 0.0f) { if (o < MAXE) cols[o] = (unsigned short)(col0);     o++; }
            if (v[j].y == 0.0f) { if (o < MAXE) cols[o] = (unsigned short)(col0 + 1); o++; }
            if (v[j].z == 0.0f) { if (o < MAXE) cols[o] = (unsigned short)(col0 + 2); o++; }
            if (v[j].w == 0.0f) { if (o < MAXE) cols[o] = (unsigned short)(col0 + 3); o++; }
            cnt += __popc(b0) + __popc(b1) + __popc(b2) + __popc(b3);
        }
    }
    if (lane == 0) g_rowcnt[m] = min(cnt, MAXE);
}

// ---------------- K4: sign-split column sums P/Q + pack sign bits into CSR ----------------
__global__ __launch_bounds__(256) void k4_z() {
    int m = blockIdx.x * 8 + (threadIdx.x >> 5);
    int lane = threadIdx.x & 31;
    int cnt = g_rowcnt[m];
    float ss0 = g_ssrc[m],      ea0 = g_ea[m],      ea20 = g_ea2[m];
    float ss1 = g_ssrc[NV + m], ea1 = g_ea[NV + m], ea21 = g_ea2[NV + m];
    unsigned short* cols = &g_cols[(size_t)m * MAXE];
    for (int e = lane; e < cnt; e += 32) {
        unsigned c = cols[e];
        int n = (int)c;
        float st0 = g_stgt[n], st1 = g_stgt[NV + n];
        if (ss0 + st0 > 0.0f) { atomicAdd(&g_PQ[n], ea0);          c |= 0x4000u; }
        else                  { atomicAdd(&g_PQ[NV + n], ea20); }
        if (ss1 + st1 > 0.0f) { atomicAdd(&g_PQ[2 * NV + n], ea1); c |= 0x2000u; }
        else                  { atomicAdd(&g_PQ[3 * NV + n], ea21); }
        cols[e] = (unsigned short)c;
    }
}

// ---------------- K5: fold Z into packed per-column coefficients ----------------
__global__ void k5_cz() {
    int n = blockIdx.x * 256 + threadIdx.x;
    if (n >= NV) return;
    float Z0 = g_eb[n] * g_PQ[n] + g_eb2[n] * g_PQ[NV + n];
    float Z1 = g_eb[NV + n] * g_PQ[2 * NV + n] + g_eb2[NV + n] * g_PQ[3 * NV + n];
    g_coefpk[n] = make_float4(0.5f * g_eb[n] / Z0,       0.5f * g_eb2[n] / Z0,
                              0.5f * g_eb[NV + n] / Z1,  0.5f * g_eb2[NV + n] / Z1);
}

// ---------------- K6: warp-per-row gather SpMM, fp16 payload, lane-split heads ----------------
// Lanes 0..15 process head0 (features 8*lane .. 8*lane+8), lanes 16..31 head1.
// One LDG.128 per warp per edge covers both heads (512B node block).
__global__ __launch_bounds__(256) void k6_spmm() {
    const int row = blockIdx.x * 8 + (threadIdx.x >> 5);
    const int lane = threadIdx.x & 31;
    const int cnt = g_rowcnt[row];
    const unsigned short* __restrict__ cp = &g_cols[(size_t)row * MAXE];
    const float4 re = __ldg(&g_rowea[row]);
    const bool h1 = lane >= 16;

    float acc[8];
#pragma unroll
    for (int j = 0; j < 8; j++) acc[j] = 0.0f;

#pragma unroll 4
    for (int e = 0; e < cnt; e++) {
        const unsigned c = cp[e];
        const int n = (int)(c & 0x1FFFu);
        const float4 q = __ldg(&g_coefpk[n]);
        const float cf = h1 ? ((c & 0x2000u) ? re.z * q.z : re.w * q.w)
                            : ((c & 0x4000u) ? re.x * q.x : re.y * q.y);
        const uint4 hv = *(const uint4*)((const char*)g_projh + (size_t)n * 512 + lane * 16);
        const half2* hp = (const half2*)&hv;
#pragma unroll
        for (int j = 0; j < 4; j++) {
            float2 f = __half22float2(hp[j]);
            acc[2 * j]     += cf * f.x;
            acc[2 * j + 1] += cf * f.y;
        }
    }
    // merge head1 partials (lanes 16..31) into lanes 0..15
#pragma unroll
    for (int j = 0; j < 8; j++) acc[j] += __shfl_down_sync(FULLMASK, acc[j], 16);
    if (lane < 16) {
        float* dst = &g_vals[(size_t)row * FD + lane * 8];
        *(float4*)dst       = make_float4(acc[0], acc[1], acc[2], acc[3]);
        *(float4*)(dst + 4) = make_float4(acc[4], acc[5], acc[6], acc[7]);
    }
}

// ---------------- K7: instance-norm stats (double accumulation) ----------------
__global__ __launch_bounds__(256) void k7_stats() {
    __shared__ double sdat[2][8];
    double s = 0.0, s2 = 0.0;
    for (int i = blockIdx.x * 256 + threadIdx.x; i < NF; i += gridDim.x * 256) {
        double v = (double)g_vals[i];
        s += v; s2 += v * v;
    }
#pragma unroll
    for (int o = 16; o; o >>= 1) {
        s  += __shfl_xor_sync(FULLMASK, s, o);
        s2 += __shfl_xor_sync(FULLMASK, s2, o);
    }
    int wid = threadIdx.x >> 5, lane = threadIdx.x & 31;
    if (lane == 0) { sdat[0][wid] = s; sdat[1][wid] = s2; }
    __syncthreads();
    if (threadIdx.x == 0) {
        double t = 0.0, t2 = 0.0;
        for (int i = 0; i < 8; i++) { t += sdat[0][i]; t2 += sdat[1][i]; }
        atomicAdd(&g_sum[0], t);
        atomicAdd(&g_sum[1], t2);
    }
}

// ---------------- K8: normalize + residual + ELU ----------------
__global__ void k8_final(float* __restrict__ out) {
    int i = blockIdx.x * 256 + threadIdx.x;
    if (i >= NF) return;
    double mu_d = g_sum[0] / (double)NF;
    double var_d = g_sum[1] / (double)NF - mu_d * mu_d;
    float mu = (float)mu_d;
    float inv = rsqrtf((float)var_d + 1e-5f);
    float v = (g_vals[i] - mu) * inv + g_res[i];
    out[i] = v > 0.0f ? v : expm1f(v);
}

// ---------------- launch ----------------
extern "C" void kernel_launch(void* const* d_in, const int* in_sizes, int n_in,
                              void* d_out, int out_size) {
    const float* x    = (const float*)d_in[0];
    const float* conn = (const float*)d_in[1];
    const float* W    = (const float*)d_in[2];
    const float* asrc = (const float*)d_in[3];
    const float* atgt = (const float*)d_in[4];
    const float* wres = (const float*)d_in[5];
    float* out = (float*)d_out;
    float* outmask = out + NF;

    k0_zero<<<128, 256>>>();
    k1_gemm<<<dim3(64, 3), 256>>>(x, W, wres);
    k1c_half<<<NF / 512, 256>>>();
    k2_scal<<<2048, 256>>>(asrc, atgt);
    k3_mask<<<1024, 256>>>((const float4*)conn, (float4*)outmask);
    k4_z<<<1024, 256>>>();
    k5_cz<<<32, 256>>>();
    k6_spmm<<<1024, 256>>>();
    k7_stats<<<512, 256>>>();
    k8_final<<<NF / 256, 256>>>(out);
}